// round 15
// baseline (speedup 1.0000x reference)
#include <cuda_runtime.h>
#include <cuda_fp16.h>
#include <math.h>

#define FDIM 128
#define HDIM 32
#define NN_MAX 100000
#define NE_MAX 3200000
#define NGRAPH 512

// ---- scratch (no allocation allowed) ----
// feature buffers stored as packed half2 (32 ch = 16 half2 = 64B per node)
__device__ __align__(128) __half2 g_tA[NN_MAX * 16];
__device__ __align__(128) __half2 g_tB[NN_MAX * 16];
__device__ __align__(128) float   g_pool[NGRAPH * HDIM];
__device__ __align__(128) int     g_deg[NN_MAX + 1];
__device__ __align__(128) int     g_off[NN_MAX + 1];
__device__ __align__(128) int     g_cursor[NN_MAX];
__device__ __align__(128) int     g_bsum[256];
__device__ __align__(128) int2    g_edge[NE_MAX];    // {col, weight bits}

// ---------------------------------------------------------------------------
// CSR build 1: degree histogram
// ---------------------------------------------------------------------------
__global__ void hist_kernel(const int* __restrict__ row, int* __restrict__ deg, int E) {
    int e0 = (blockIdx.x * blockDim.x + threadIdx.x) * 4;
    if (e0 + 3 < E) {
        int4 r = *(const int4*)(row + e0);
        atomicAdd(&deg[r.x], 1);
        atomicAdd(&deg[r.y], 1);
        atomicAdd(&deg[r.z], 1);
        atomicAdd(&deg[r.w], 1);
    } else {
        for (int e = e0; e < E; e++) atomicAdd(&deg[row[e]], 1);
    }
}

// ---------------------------------------------------------------------------
// CSR build 2a: per-block exclusive scan + block sums
// ---------------------------------------------------------------------------
__global__ void scan1_kernel(const int* __restrict__ deg, int* __restrict__ off,
                             int* __restrict__ bsum, int N) {
    __shared__ int ws[32];
    int tid = threadIdx.x, lane = tid & 31, wid = tid >> 5;
    int i = blockIdx.x * 1024 + tid;
    int v = (i < N) ? deg[i] : 0;
    int x = v;
#pragma unroll
    for (int d = 1; d < 32; d <<= 1) {
        int y = __shfl_up_sync(0xffffffffu, x, d);
        if (lane >= d) x += y;
    }
    if (lane == 31) ws[wid] = x;
    __syncthreads();
    if (wid == 0) {
        int s = ws[lane];
        int xs = s;
#pragma unroll
        for (int d = 1; d < 32; d <<= 1) {
            int y = __shfl_up_sync(0xffffffffu, xs, d);
            if (lane >= d) xs += y;
        }
        ws[lane] = xs - s;
    }
    __syncthreads();
    int excl = ws[wid] + (x - v);
    if (i < N) off[i] = excl;
    if (tid == 1023) bsum[blockIdx.x] = excl + v;
}

// ---------------------------------------------------------------------------
// CSR build 2b: scan block sums (single 128-thread block, nb <= 128)
// ---------------------------------------------------------------------------
__global__ void scan2_kernel(int* __restrict__ bsum, int nb, int* __restrict__ offN) {
    __shared__ int ws[4];
    int tid = threadIdx.x, lane = tid & 31, wid = tid >> 5;
    int v = (tid < nb) ? bsum[tid] : 0;
    int x = v;
#pragma unroll
    for (int d = 1; d < 32; d <<= 1) {
        int y = __shfl_up_sync(0xffffffffu, x, d);
        if (lane >= d) x += y;
    }
    if (lane == 31) ws[wid] = x;
    __syncthreads();
    int add = 0;
#pragma unroll
    for (int j = 0; j < 4; j++)
        if (j < wid) add += ws[j];
    int excl = add + (x - v);
    if (tid < nb) bsum[tid] = excl;
    if (tid == 127) *offN = excl + v;
}

// ---------------------------------------------------------------------------
// CSR build 2c: add block bases; produce cursor copy
// ---------------------------------------------------------------------------
__global__ void scan3_kernel(int* __restrict__ off, const int* __restrict__ bsum,
                             int* __restrict__ cursor, int N) {
    int i = blockIdx.x * 1024 + threadIdx.x;
    if (i < N) {
        int o = off[i] + bsum[blockIdx.x];
        off[i] = o;
        cursor[i] = o;
    }
}

// ---------------------------------------------------------------------------
// CSR build 3: scatter edges (interleaved int2 {col, w bits})
// ---------------------------------------------------------------------------
__global__ void scatter_kernel(const int* __restrict__ row, const int* __restrict__ col,
                               const float* __restrict__ w,
                               int* __restrict__ cursor, int2* __restrict__ edge, int E) {
    int e = blockIdx.x * blockDim.x + threadIdx.x;
    if (e >= E) return;
    int r = row[e];
    int pos = atomicAdd(&cursor[r], 1);
    edge[pos] = make_int2(col[e], __float_as_int(w[e]));
}

// ---------------------------------------------------------------------------
// half2 store helper: lane holds float o for channel `lane`; even lanes store
// the (o, o_next) pair. dst points to the node's 16-half2 row.
// ---------------------------------------------------------------------------
__device__ __forceinline__ void store_row_half(__half2* dst, float o, int lane) {
    float o1 = __shfl_down_sync(0xffffffffu, o, 1);
    if ((lane & 1) == 0)
        dst[lane >> 1] = __floats2half2_rn(o, o1);
}

// ---------------------------------------------------------------------------
// GEMM1: t = x @ W1 ([N,128]@[128,32]) -> fp16 features
// 32-row tile; padded transposed W in smem (1 LDS.128 per 4-k per lane).
// ---------------------------------------------------------------------------
#define WPAD 132
__global__ void gemm1_kernel(const float* __restrict__ x,
                             const float* __restrict__ W,
                             __half2* __restrict__ t, int N) {
    __shared__ float sWT[HDIM * WPAD];
    __shared__ float sx[32 * FDIM];
    int tid = threadIdx.x;
    int warp = tid >> 5, lane = tid & 31;
    for (int i = tid; i < FDIM * HDIM; i += 256) {
        int k = i >> 5, c = i & 31;
        sWT[c * WPAD + k] = W[i];
    }

    for (long base = (long)blockIdx.x * 32; base < N; base += (long)gridDim.x * 32) {
        int nrows = (int)min((long)32, (long)N - base);
        __syncthreads();
        int nquads = nrows * (FDIM / 4);
        const float4* src = (const float4*)(x + base * FDIM);
        for (int i = tid; i < nquads; i += 256)
            ((float4*)sx)[i] = src[i];
        __syncthreads();

        int r0 = warp * 4;
        float a[4] = {0.f, 0.f, 0.f, 0.f};
        const float* xb = sx + r0 * FDIM;
        const float* wt = sWT + lane * WPAD;
#pragma unroll 8
        for (int k = 0; k < FDIM; k += 4) {
            float4 wq = *(const float4*)(wt + k);
#pragma unroll
            for (int r = 0; r < 4; r++) {
                float4 xq = *(const float4*)(xb + r * FDIM + k);
                a[r] += xq.x * wq.x + xq.y * wq.y + xq.z * wq.z + xq.w * wq.w;
            }
        }
#pragma unroll
        for (int r = 0; r < 4; r++)
            if (r0 + r < nrows)
                store_row_half(t + (base + r0 + r) * 16, a[r], lane);
    }
}

// ---------------------------------------------------------------------------
// Gather core (fp16 features): warp per node; 4 groups x 8 lanes.
// Each lane loads 8B (4 channels) per edge; 64B per row total.
// Result (channels 4*(lane&7)..+3) valid in ALL lanes after butterfly.
// ---------------------------------------------------------------------------
__device__ __forceinline__ float4 fetch4(const uint2* __restrict__ tin, int c, int l) {
    uint2 raw = tin[c * 8 + l];
    float2 f0 = __half22float2(*(const __half2*)&raw.x);
    float2 f1 = __half22float2(*(const __half2*)&raw.y);
    return make_float4(f0.x, f0.y, f1.x, f1.y);
}

__device__ __forceinline__ float4 csr_gather(const int* __restrict__ off,
                                             const int2* __restrict__ edge,
                                             const uint2* __restrict__ tin,
                                             int n, int lane) {
    int grp = lane >> 3;
    int l   = lane & 7;
    int s = off[n], e1 = off[n + 1];
    float4 a = make_float4(0.f, 0.f, 0.f, 0.f);

    int e = s;
    for (; e + 16 <= e1; e += 16) {
        int i0 = e + grp;
        int2 E0 = edge[i0];
        int2 E1 = edge[i0 + 4];
        int2 E2 = edge[i0 + 8];
        int2 E3 = edge[i0 + 12];
        float w0 = __int_as_float(E0.y);
        float w1 = __int_as_float(E1.y);
        float w2 = __int_as_float(E2.y);
        float w3 = __int_as_float(E3.y);
        float4 v0 = fetch4(tin, E0.x, l);
        float4 v1 = fetch4(tin, E1.x, l);
        float4 v2 = fetch4(tin, E2.x, l);
        float4 v3 = fetch4(tin, E3.x, l);
        a.x += w0*v0.x + w1*v1.x + w2*v2.x + w3*v3.x;
        a.y += w0*v0.y + w1*v1.y + w2*v2.y + w3*v3.y;
        a.z += w0*v0.z + w1*v1.z + w2*v2.z + w3*v3.z;
        a.w += w0*v0.w + w1*v1.w + w2*v2.w + w3*v3.w;
    }
    for (; e < e1; e += 4) {
        int i = e + grp;
        int2 Ee = (i < e1) ? edge[i] : make_int2(0, 0);
        float wt = __int_as_float(Ee.y);
        float4 v = fetch4(tin, Ee.x, l);
        a.x += wt * v.x; a.y += wt * v.y; a.z += wt * v.z; a.w += wt * v.w;
    }
#pragma unroll
    for (int d = 8; d <= 16; d <<= 1) {
        a.x += __shfl_xor_sync(0xffffffffu, a.x, d);
        a.y += __shfl_xor_sync(0xffffffffu, a.y, d);
        a.z += __shfl_xor_sync(0xffffffffu, a.z, d);
        a.w += __shfl_xor_sync(0xffffffffu, a.w, d);
    }
    return a;
}

__device__ __forceinline__ float4 elu4(float4 a) {
    a.x = a.x > 0.f ? a.x : (expf(a.x) - 1.f);
    a.y = a.y > 0.f ? a.y : (expf(a.y) - 1.f);
    a.z = a.z > 0.f ? a.z : (expf(a.z) - 1.f);
    a.w = a.w > 0.f ? a.w : (expf(a.w) - 1.f);
    return a;
}

// ---------------------------------------------------------------------------
// Fused layer: tout[n] = (elu(spmm(tin)[n] + b)) @ Wnext   (fp16 in/out)
// ---------------------------------------------------------------------------
__global__ void spmm_fused_kernel(const int* __restrict__ off,
                                  const int2* __restrict__ edge,
                                  const uint2* __restrict__ tin,
                                  const float* __restrict__ b,
                                  const float* __restrict__ W,
                                  __half2* __restrict__ tout, int N) {
    __shared__ float sW[HDIM * HDIM];
    __shared__ float sb[HDIM];
    int tid = threadIdx.x;
    for (int i = tid; i < HDIM * HDIM; i += blockDim.x) sW[i] = W[i];
    if (tid < HDIM) sb[tid] = b[tid];
    __syncthreads();

    int lane = tid & 31;
    int n = (blockIdx.x * blockDim.x + tid) >> 5;
    if (n >= N) return;

    float4 a = csr_gather(off, edge, tin, n, lane);
    int l = lane & 7;
    float4 vb = *(const float4*)(sb + 4 * l);
    a.x += vb.x; a.y += vb.y; a.z += vb.z; a.w += vb.w;
    a = elu4(a);

    float o = 0.f;
#pragma unroll
    for (int q = 0; q < 8; q++) {
        float hx = __shfl_sync(0xffffffffu, a.x, q);
        float hy = __shfl_sync(0xffffffffu, a.y, q);
        float hz = __shfl_sync(0xffffffffu, a.z, q);
        float hw = __shfl_sync(0xffffffffu, a.w, q);
        o += hx * sW[(4*q+0) * HDIM + lane]
           + hy * sW[(4*q+1) * HDIM + lane]
           + hz * sW[(4*q+2) * HDIM + lane]
           + hw * sW[(4*q+3) * HDIM + lane];
    }
    store_row_half(tout + n * 16, o, lane);
}

// ---------------------------------------------------------------------------
// Final layer fused with pool: pool[seg[n]] += elu(spmm(tin)[n] + b3)  (fp32)
// ---------------------------------------------------------------------------
__global__ void spmm_pool_kernel(const int* __restrict__ off,
                                 const int2* __restrict__ edge,
                                 const uint2* __restrict__ tin,
                                 const float* __restrict__ b,
                                 const int* __restrict__ seg,
                                 float* __restrict__ pool, int N) {
    __shared__ float sb[HDIM];
    int tid = threadIdx.x;
    if (tid < HDIM) sb[tid] = b[tid];
    __syncthreads();

    int lane = tid & 31;
    int n = (blockIdx.x * blockDim.x + tid) >> 5;
    if (n >= N) return;

    float4 a = csr_gather(off, edge, tin, n, lane);
    int l = lane & 7;
    float4 vb = *(const float4*)(sb + 4 * l);
    a.x += vb.x; a.y += vb.y; a.z += vb.z; a.w += vb.w;
    a = elu4(a);

    if (lane < 8) {
        float4* dst = (float4*)(pool + seg[n] * HDIM) + l;
        asm volatile("red.global.add.v4.f32 [%0], {%1,%2,%3,%4};"
                     :: "l"(__cvta_generic_to_global(dst)),
                        "f"(a.x), "f"(a.y), "f"(a.z), "f"(a.w)
                     : "memory");
    }
}

// ---------------------------------------------------------------------------
// MLP head (fp32)
// ---------------------------------------------------------------------------
__global__ void mlp_kernel(const float* __restrict__ pool,
                           const float* __restrict__ W1, const float* __restrict__ b1,
                           const float* __restrict__ W2, const float* __restrict__ b2,
                           const float* __restrict__ W3, const float* __restrict__ b3,
                           float* __restrict__ out) {
    __shared__ float sW1[32 * 64], sW2[64 * 32], sW3[32], sb1[64], sb2[32];
    int tid = threadIdx.x;
    for (int i = tid; i < 2048; i += blockDim.x) { sW1[i] = W1[i]; sW2[i] = W2[i]; }
    if (tid < 64) sb1[tid] = b1[tid];
    if (tid < 32) { sW3[tid] = W3[tid]; sb2[tid] = b2[tid]; }
    __syncthreads();

    int g = blockIdx.x * blockDim.x + tid;
    if (g >= NGRAPH) return;
    float in[32];
#pragma unroll
    for (int c = 0; c < 32; c++) in[c] = pool[g * 32 + c];
    float h2[32];
#pragma unroll
    for (int c = 0; c < 32; c++) h2[c] = sb2[c];
    for (int j = 0; j < 64; j++) {
        float t = sb1[j];
#pragma unroll
        for (int c = 0; c < 32; c++) t += in[c] * sW1[c * 64 + j];
        t = fmaxf(t, 0.f);
#pragma unroll
        for (int c = 0; c < 32; c++) h2[c] += t * sW2[j * 32 + c];
    }
    float o = b3[0];
#pragma unroll
    for (int c = 0; c < 32; c++) o += fmaxf(h2[c], 0.f) * sW3[c];
    out[g] = 1.f / (1.f + expf(-o));
}

// ---------------------------------------------------------------------------
extern "C" void kernel_launch(void* const* d_in, const int* in_sizes, int n_in,
                              void* d_out, int out_size) {
    const float* x   = (const float*)d_in[0];
    const int*   ei  = (const int*)  d_in[1];
    const float* ew  = (const float*)d_in[2];
    const int*   seg = (const int*)  d_in[3];
    const float* W1  = (const float*)d_in[4];
    const float* b1  = (const float*)d_in[5];
    const float* W2  = (const float*)d_in[6];
    const float* b2  = (const float*)d_in[7];
    const float* W3  = (const float*)d_in[8];
    const float* b3  = (const float*)d_in[9];
    const float* Wd1 = (const float*)d_in[10];
    const float* bd1 = (const float*)d_in[11];
    const float* Wd2 = (const float*)d_in[12];
    const float* bd2 = (const float*)d_in[13];
    const float* Wd3 = (const float*)d_in[14];
    const float* bd3 = (const float*)d_in[15];
    float* out = (float*)d_out;

    int N = in_sizes[0] / FDIM;
    int E = in_sizes[1] / 2;
    const int* row = ei;
    const int* col = ei + E;

    __half2 *tA, *tB;
    float *pool;
    int *deg, *off, *cursor, *bsum;
    int2 *edge;
    cudaGetSymbolAddress((void**)&tA,     g_tA);
    cudaGetSymbolAddress((void**)&tB,     g_tB);
    cudaGetSymbolAddress((void**)&pool,   g_pool);
    cudaGetSymbolAddress((void**)&deg,    g_deg);
    cudaGetSymbolAddress((void**)&off,    g_off);
    cudaGetSymbolAddress((void**)&cursor, g_cursor);
    cudaGetSymbolAddress((void**)&bsum,   g_bsum);
    cudaGetSymbolAddress((void**)&edge,   g_edge);

    int warpBlocks = (N * 32 + 255) / 256;
    int nb = (N + 1023) / 1024;

    // ---- CSR build (amortized over 3 layers) ----
    cudaMemsetAsync(deg, 0, (size_t)(N + 1) * sizeof(int));
    hist_kernel<<<(E / 4 + 255) / 256 + 1, 256>>>(row, deg, E);
    scan1_kernel<<<nb, 1024>>>(deg, off, bsum, N);
    scan2_kernel<<<1, 128>>>(bsum, nb, off + N);
    scan3_kernel<<<nb, 1024>>>(off, bsum, cursor, N);
    scatter_kernel<<<(E + 255) / 256, 256>>>(row, col, ew, cursor, edge, E);

    // ---- projection + fused GCN layers (fp16 features) ----
    gemm1_kernel<<<(N + 31) / 32, 256>>>(x, W1, tA, N);
    spmm_fused_kernel<<<warpBlocks, 256>>>(off, edge, (const uint2*)tA, b1, W2, tB, N);
    spmm_fused_kernel<<<warpBlocks, 256>>>(off, edge, (const uint2*)tB, b2, W3, tA, N);

    // ---- final layer + pool + head ----
    cudaMemsetAsync(pool, 0, (size_t)NGRAPH * HDIM * sizeof(float));
    spmm_pool_kernel<<<warpBlocks, 256>>>(off, edge, (const uint2*)tA, b3, seg, pool, N);
    mlp_kernel<<<2, 256>>>(pool, Wd1, bd1, Wd2, bd2, Wd3, bd3, out);
}